// round 8
// baseline (speedup 1.0000x reference)
#include <cuda_runtime.h>
#include <cuda_fp16.h>
#include <cstdint>

#define BATCH 32
#define TDIM  2048
#define CDIM  384
#define HDIM  64
#define BT    (BATCH * TDIM)
#define NQT   32

// Projected activations in f16 (proj rounds once; q pre-scaled by 0.125).
// V stored transposed: g_vt[b][h][t].
__device__ __align__(256) __half g_q [BT * HDIM];
__device__ __align__(256) __half g_k [BT * HDIM];
__device__ __align__(256) __half g_vt[BATCH * HDIM * TDIM];

__device__ __forceinline__ float tf32r(float x) {
    asm("cvt.rna.tf32.f32 %0, %1;" : "=f"(x) : "f"(x));
    return x;
}
__device__ __forceinline__ uint32_t fu(float x) { return __float_as_uint(x); }
__device__ __forceinline__ uint32_t packh2(float lo, float hi) {
    uint32_t r;
    asm("cvt.rn.f16x2.f32 %0, %1, %2;" : "=r"(r) : "f"(hi), "f"(lo));
    return r;
}
__device__ __forceinline__ uint32_t smem_u32(const void* p) {
    uint32_t a;
    asm("{ .reg .u64 t; cvta.to.shared.u64 t, %1; cvt.u32.u64 %0, t; }"
        : "=r"(a) : "l"(p));
    return a;
}
__device__ __forceinline__ void cpa16(uint32_t dst, const void* src) {
    asm volatile("cp.async.cg.shared.global [%0], [%1], 16;"
                 :: "r"(dst), "l"(src));
}
#define CPCOMMIT() asm volatile("cp.async.commit_group;" ::: "memory")
#define CPWAIT(n)  asm volatile("cp.async.wait_group %0;" :: "n"(n) : "memory")

// tf32 m16n8k8 (proj only)
__device__ __forceinline__ void mma8(float4& c, const uint32_t a[4],
                                     uint32_t b0, uint32_t b1) {
    asm volatile(
        "mma.sync.aligned.m16n8k8.row.col.f32.tf32.tf32.f32 "
        "{%0,%1,%2,%3}, {%4,%5,%6,%7}, {%8,%9}, {%0,%1,%2,%3};"
        : "+f"(c.x), "+f"(c.y), "+f"(c.z), "+f"(c.w)
        : "r"(a[0]), "r"(a[1]), "r"(a[2]), "r"(a[3]), "r"(b0), "r"(b1));
}
// f16 m16n8k16, fp32 accum (attn).
// A frag (u32 = f16x2): a0(r=l>>2, k=2q,2q+1) a1(r+8,same) a2(r,k+8..9) a3(r+8,k+8..9)
// B frag: b0(k=2q..2q+1, n=l>>2) b1(k+8..9, n)
// C frag: c0(r,2q) c1(r,2q+1) c2(r+8,2q) c3(r+8,2q+1)
__device__ __forceinline__ void mma16(float4& c, const uint32_t a[4],
                                      uint32_t b0, uint32_t b1) {
    asm volatile(
        "mma.sync.aligned.m16n8k16.row.col.f32.f16.f16.f32 "
        "{%0,%1,%2,%3}, {%4,%5,%6,%7}, {%8,%9}, {%0,%1,%2,%3};"
        : "+f"(c.x), "+f"(c.y), "+f"(c.z), "+f"(c.w)
        : "r"(a[0]), "r"(a[1]), "r"(a[2]), "r"(a[3]), "r"(b0), "r"(b1));
}

// ---------------------------------------------------------------------------
// Projection: [K|Q|V] = x @ [Wk|Wq|Wv], tf32 MMA. Block = 256 thr, 128 rows.
// Epilogue writes f16 (q scaled by 0.125, V transposed into g_vt).
// ---------------------------------------------------------------------------
__global__ __launch_bounds__(256, 1) void proj_kernel(
    const float* __restrict__ x,
    const float* __restrict__ Wk,
    const float* __restrict__ Wq,
    const float* __restrict__ Wv)
{
    __shared__ float Xs[128 * 36];
    __shared__ float Ws[3 * 32 * 72];

    const int t    = threadIdx.x;
    const int warp = t >> 5;
    const int lane = t & 31;
    const int q    = lane & 3;
    const int r4   = lane >> 2;
    const int row0 = blockIdx.x * 128;
    const float* Wm[3] = {Wk, Wq, Wv};

    float4 c[24];
    #pragma unroll
    for (int i = 0; i < 24; i++) c[i] = make_float4(0.f, 0.f, 0.f, 0.f);

    float4 xr[4], wr[6];
    #pragma unroll
    for (int i = 0; i < 4; i++) {
        int f = t + i * 256, r = f >> 3, c4 = f & 7;
        xr[i] = *(const float4*)&x[(row0 + r) * CDIM + c4 * 4];
    }
    #pragma unroll
    for (int j = 0; j < 6; j++) {
        int g = t + (j & 1) * 256, k = g >> 4, h4 = g & 15;
        wr[j] = *(const float4*)&Wm[j >> 1][k * HDIM + h4 * 4];
    }

    for (int cc = 0; cc < 12; cc++) {
        __syncthreads();
        #pragma unroll
        for (int i = 0; i < 4; i++) {
            int f = t + i * 256, r = f >> 3, c4 = f & 7;
            *(float4*)&Xs[r * 36 + c4 * 4] = make_float4(
                tf32r(xr[i].x), tf32r(xr[i].y), tf32r(xr[i].z), tf32r(xr[i].w));
        }
        #pragma unroll
        for (int j = 0; j < 6; j++) {
            int g = t + (j & 1) * 256, k = g >> 4, h4 = g & 15;
            *(float4*)&Ws[(j >> 1) * 2304 + k * 72 + h4 * 4] = make_float4(
                tf32r(wr[j].x), tf32r(wr[j].y), tf32r(wr[j].z), tf32r(wr[j].w));
        }
        __syncthreads();

        if (cc + 1 < 12) {
            const int c0 = (cc + 1) * 32;
            #pragma unroll
            for (int i = 0; i < 4; i++) {
                int f = t + i * 256, r = f >> 3, c4 = f & 7;
                xr[i] = *(const float4*)&x[(row0 + r) * CDIM + c0 + c4 * 4];
            }
            #pragma unroll
            for (int j = 0; j < 6; j++) {
                int g = t + (j & 1) * 256, k = g >> 4, h4 = g & 15;
                wr[j] = *(const float4*)&Wm[j >> 1][(c0 + k) * HDIM + h4 * 4];
            }
        }

        uint32_t a[4][4];
        #pragma unroll
        for (int kc = 0; kc < 4; kc++) {
            const int rb = (warp * 16 + r4) * 36 + 8 * kc + q;
            a[kc][0] = fu(Xs[rb]);
            a[kc][1] = fu(Xs[rb + 8 * 36]);
            a[kc][2] = fu(Xs[rb + 4]);
            a[kc][3] = fu(Xs[rb + 8 * 36 + 4]);
        }
        #pragma unroll
        for (int mat = 0; mat < 3; mat++)
            #pragma unroll
            for (int nc = 0; nc < 8; nc++)
                #pragma unroll
                for (int kc = 0; kc < 4; kc++) {
                    uint32_t b0 = fu(Ws[mat * 2304 + (8 * kc + q)     * 72 + 8 * nc + r4]);
                    uint32_t b1 = fu(Ws[mat * 2304 + (8 * kc + q + 4) * 72 + 8 * nc + r4]);
                    mma8(c[mat * 8 + nc], a[kc], b0, b1);
                }
    }

    const int row = row0 + warp * 16 + r4;
    const int bb  = row >> 11, tin = row & 2047;
    #pragma unroll
    for (int nc = 0; nc < 8; nc++) {
        const int col = 8 * nc + 2 * q;
        // K
        float4 v = c[nc];
        *(uint32_t*)&g_k[row * HDIM + col]       = packh2(v.x, v.y);
        *(uint32_t*)&g_k[(row + 8) * HDIM + col] = packh2(v.z, v.w);
        // Q (pre-scaled)
        v = c[8 + nc];
        *(uint32_t*)&g_q[row * HDIM + col]       = packh2(v.x * 0.125f, v.y * 0.125f);
        *(uint32_t*)&g_q[(row + 8) * HDIM + col] = packh2(v.z * 0.125f, v.w * 0.125f);
        // V transposed: g_vt[bb][h][t]
        v = c[16 + nc];
        __half* vt = g_vt + (size_t)bb * (HDIM * TDIM) + tin;
        vt[(size_t)col * TDIM]           = __float2half(v.x);
        vt[(size_t)(col + 1) * TDIM]     = __float2half(v.y);
        vt[(size_t)col * TDIM + 8]       = __float2half(v.z);
        vt[(size_t)(col + 1) * TDIM + 8] = __float2half(v.w);
    }
}

// ---------------------------------------------------------------------------
// Flash attention, f16 m16n8k16 warp-MMA. Block = 128 thr (4 warps), 64 rows.
// grid (32, 32), heavy tiles first. K [key][h] and Vt [h][key] staged f16 via
// cp.async, double-buffered. Pitch = 36 words (72 halves) -> conflict-free.
// ---------------------------------------------------------------------------
#define PW    36                       // pitch in 32-bit words
#define TILEW (64 * PW)                // words per 64x64 f16 tile

__global__ __launch_bounds__(128, 3) void attn_kernel(float* __restrict__ out)
{
    __shared__ uint32_t Kbuf[2][TILEW];
    __shared__ uint32_t Vbuf[2][TILEW];

    const int t    = threadIdx.x;
    const int b    = blockIdx.y;
    const int warp = t >> 5;
    const int lane = t & 31;
    const int q    = lane & 3;
    const int r4   = lane >> 2;

    const int qt     = (NQT - 1) - (int)blockIdx.x;   // heavy first
    const int nkt    = qt + 1;
    const int row_lo = qt * 64 + warp * 16 + r4;

    const __half* kb0 = g_k + (size_t)(b * TDIM) * HDIM;
    const __half* vt0 = g_vt + (size_t)b * (HDIM * TDIM);

    auto stage = [&](int kt, int buf) {
        const __half* kb = kb0 + (size_t)kt * 64 * HDIM;
        const __half* vb = vt0 + kt * 64;
        const uint32_t kd = smem_u32(Kbuf[buf]);
        const uint32_t vd = smem_u32(Vbuf[buf]);
        #pragma unroll
        for (int i = 0; i < 4; i++) {
            int f = t + i * 128, r = f >> 3, ch = f & 7;   // 8x16B per 128B row
            cpa16(kd + (uint32_t)(r * PW + ch * 4) * 4u, kb + r * HDIM + ch * 8);
            cpa16(vd + (uint32_t)(r * PW + ch * 4) * 4u, vb + (size_t)r * TDIM + ch * 8);
        }
        CPCOMMIT();
    };

    stage(0, 0);

    // Q fragments (f16, already scaled)
    uint32_t qa[4][4];
    {
        const __half* qp = g_q + (size_t)(b * TDIM + row_lo) * HDIM;
        #pragma unroll
        for (int kc = 0; kc < 4; kc++) {
            qa[kc][0] = *(const uint32_t*)&qp[16 * kc + 2 * q];
            qa[kc][1] = *(const uint32_t*)&qp[8 * HDIM + 16 * kc + 2 * q];
            qa[kc][2] = *(const uint32_t*)&qp[16 * kc + 2 * q + 8];
            qa[kc][3] = *(const uint32_t*)&qp[8 * HDIM + 16 * kc + 2 * q + 8];
        }
    }

    float4 o[8];
    #pragma unroll
    for (int i = 0; i < 8; i++) o[i] = make_float4(0.f, 0.f, 0.f, 0.f);
    float m0 = -1e30f, m1 = -1e30f, l0 = 0.f, l1 = 0.f;

    for (int kt = 0; kt < nkt; kt++) {
        if (kt + 1 < nkt) { stage(kt + 1, (kt + 1) & 1); CPWAIT(1); }
        else              { CPWAIT(0); }
        __syncthreads();

        const uint32_t* Ku = Kbuf[kt & 1];
        const uint32_t* Vu = Vbuf[kt & 1];

        // S = Q @ K^T
        float4 st[8];
        #pragma unroll
        for (int i = 0; i < 8; i++) st[i] = make_float4(0.f, 0.f, 0.f, 0.f);
        #pragma unroll
        for (int nc = 0; nc < 8; nc++) {
            const uint32_t* kr = Ku + (8 * nc + r4) * PW;
            #pragma unroll
            for (int kc = 0; kc < 4; kc++)
                mma16(st[nc], qa[kc], kr[8 * kc + q], kr[8 * kc + 4 + q]);
        }

        // causal mask: only the diagonal (last) tile clips
        if (kt == nkt - 1) {
            const int cb = kt * 64 + 2 * q;
            #pragma unroll
            for (int nc = 0; nc < 8; nc++) {
                const int col = cb + 8 * nc;
                if (col > row_lo)         st[nc].x = -1e30f;
                if (col + 1 > row_lo)     st[nc].y = -1e30f;
                if (col > row_lo + 8)     st[nc].z = -1e30f;
                if (col + 1 > row_lo + 8) st[nc].w = -1e30f;
            }
        }

        // online softmax (rows r4 / r4+8, spread across the quad)
        float mx0 = st[0].x, mx1 = st[0].z;
        #pragma unroll
        for (int nc = 0; nc < 8; nc++) {
            mx0 = fmaxf(mx0, fmaxf(st[nc].x, st[nc].y));
            mx1 = fmaxf(mx1, fmaxf(st[nc].z, st[nc].w));
        }
        mx0 = fmaxf(mx0, __shfl_xor_sync(0xffffffffu, mx0, 1));
        mx0 = fmaxf(mx0, __shfl_xor_sync(0xffffffffu, mx0, 2));
        mx1 = fmaxf(mx1, __shfl_xor_sync(0xffffffffu, mx1, 1));
        mx1 = fmaxf(mx1, __shfl_xor_sync(0xffffffffu, mx1, 2));
        const float mn0 = fmaxf(m0, mx0), mn1 = fmaxf(m1, mx1);
        const float corr0 = __expf(m0 - mn0), corr1 = __expf(m1 - mn1);
        m0 = mn0; m1 = mn1;

        float s0 = 0.f, s1 = 0.f;
        #pragma unroll
        for (int nc = 0; nc < 8; nc++) {
            st[nc].x = __expf(st[nc].x - mn0);
            st[nc].y = __expf(st[nc].y - mn0);
            st[nc].z = __expf(st[nc].z - mn1);
            st[nc].w = __expf(st[nc].w - mn1);
            s0 += st[nc].x + st[nc].y;
            s1 += st[nc].z + st[nc].w;
        }
        l0 = l0 * corr0 + s0;
        l1 = l1 * corr1 + s1;
        #pragma unroll
        for (int nc = 0; nc < 8; nc++) {
            o[nc].x *= corr0; o[nc].y *= corr0;
            o[nc].z *= corr1; o[nc].w *= corr1;
        }

        // O += P @ V.  P C-frags map DIRECTLY to f16 A-frags (no shuffles).
        #pragma unroll
        for (int kc = 0; kc < 4; kc++) {
            uint32_t a[4];
            a[0] = packh2(st[2 * kc].x,     st[2 * kc].y);
            a[1] = packh2(st[2 * kc].z,     st[2 * kc].w);
            a[2] = packh2(st[2 * kc + 1].x, st[2 * kc + 1].y);
            a[3] = packh2(st[2 * kc + 1].z, st[2 * kc + 1].w);
            #pragma unroll
            for (int nc = 0; nc < 8; nc++) {
                const uint32_t* vr = Vu + (8 * nc + r4) * PW + 8 * kc;
                mma16(o[nc], a, vr[q], vr[q + 4]);
            }
        }
        __syncthreads();   // reads done before next iteration's cp.async
    }

    // epilogue
    l0 += __shfl_xor_sync(0xffffffffu, l0, 1);
    l0 += __shfl_xor_sync(0xffffffffu, l0, 2);
    l1 += __shfl_xor_sync(0xffffffffu, l1, 1);
    l1 += __shfl_xor_sync(0xffffffffu, l1, 2);
    const float inv0 = 1.0f / l0, inv1 = 1.0f / l1;

    float* ob = out + (size_t)(b * TDIM + row_lo) * HDIM;
    #pragma unroll
    for (int nc = 0; nc < 8; nc++) {
        const int col = 8 * nc + 2 * q;
        *(float2*)&ob[col]            = make_float2(o[nc].x * inv0, o[nc].y * inv0);
        *(float2*)&ob[8 * HDIM + col] = make_float2(o[nc].z * inv1, o[nc].w * inv1);
    }
}

// ---------------------------------------------------------------------------
extern "C" void kernel_launch(void* const* d_in, const int* in_sizes, int n_in,
                              void* d_out, int out_size)
{
    const float* x  = (const float*)d_in[0];
    const float* Wk = (const float*)d_in[1];
    const float* Wq = (const float*)d_in[2];
    const float* Wv = (const float*)d_in[3];
    float* out = (float*)d_out;

    proj_kernel<<<BT / 128, 256>>>(x, Wk, Wq, Wv);

    dim3 agrid(NQT, BATCH);
    attn_kernel<<<agrid, 128>>>(out);
}

// round 9
// speedup vs baseline: 1.5844x; 1.5844x over previous
#include <cuda_runtime.h>
#include <cuda_fp16.h>
#include <cstdint>

#define BATCH 32
#define TDIM  2048
#define CDIM  384
#define HDIM  64
#define BT    (BATCH * TDIM)
#define NQT   32

// Projected activations in f16 (proj rounds once; q pre-scaled by 0.125).
__device__ __align__(256) __half g_q[BT * HDIM];
__device__ __align__(256) __half g_k[BT * HDIM];
__device__ __align__(256) __half g_v[BT * HDIM];

__device__ __forceinline__ float tf32r(float x) {
    asm("cvt.rna.tf32.f32 %0, %1;" : "=f"(x) : "f"(x));
    return x;
}
__device__ __forceinline__ uint32_t fu(float x) { return __float_as_uint(x); }
__device__ __forceinline__ uint32_t packh2(float lo, float hi) {
    uint32_t r;
    asm("cvt.rn.f16x2.f32 %0, %1, %2;" : "=r"(r) : "f"(hi), "f"(lo));
    return r;
}
__device__ __forceinline__ uint32_t smem_u32(const void* p) {
    uint32_t a;
    asm("{ .reg .u64 t; cvta.to.shared.u64 t, %1; cvt.u32.u64 %0, t; }"
        : "=r"(a) : "l"(p));
    return a;
}
__device__ __forceinline__ void cpa16(uint32_t dst, const void* src) {
    asm volatile("cp.async.cg.shared.global [%0], [%1], 16;"
                 :: "r"(dst), "l"(src));
}
#define CPCOMMIT() asm volatile("cp.async.commit_group;" ::: "memory")
#define CPWAIT(n)  asm volatile("cp.async.wait_group %0;" :: "n"(n) : "memory")

__device__ __forceinline__ void ldm4(uint32_t& r0, uint32_t& r1,
                                     uint32_t& r2, uint32_t& r3, uint32_t a) {
    asm volatile("ldmatrix.sync.aligned.m8n8.x4.shared.b16 {%0,%1,%2,%3}, [%4];"
                 : "=r"(r0), "=r"(r1), "=r"(r2), "=r"(r3) : "r"(a));
}
__device__ __forceinline__ void ldm4t(uint32_t& r0, uint32_t& r1,
                                      uint32_t& r2, uint32_t& r3, uint32_t a) {
    asm volatile("ldmatrix.sync.aligned.m8n8.x4.trans.shared.b16 {%0,%1,%2,%3}, [%4];"
                 : "=r"(r0), "=r"(r1), "=r"(r2), "=r"(r3) : "r"(a));
}

// tf32 m16n8k8 (proj only)
__device__ __forceinline__ void mma8(float4& c, const uint32_t a[4],
                                     uint32_t b0, uint32_t b1) {
    asm volatile(
        "mma.sync.aligned.m16n8k8.row.col.f32.tf32.tf32.f32 "
        "{%0,%1,%2,%3}, {%4,%5,%6,%7}, {%8,%9}, {%0,%1,%2,%3};"
        : "+f"(c.x), "+f"(c.y), "+f"(c.z), "+f"(c.w)
        : "r"(a[0]), "r"(a[1]), "r"(a[2]), "r"(a[3]), "r"(b0), "r"(b1));
}
// f16 m16n8k16, fp32 accum (attn).
__device__ __forceinline__ void mma16(float4& c, const uint32_t a[4],
                                      uint32_t b0, uint32_t b1) {
    asm volatile(
        "mma.sync.aligned.m16n8k16.row.col.f32.f16.f16.f32 "
        "{%0,%1,%2,%3}, {%4,%5,%6,%7}, {%8,%9}, {%0,%1,%2,%3};"
        : "+f"(c.x), "+f"(c.y), "+f"(c.z), "+f"(c.w)
        : "r"(a[0]), "r"(a[1]), "r"(a[2]), "r"(a[3]), "r"(b0), "r"(b1));
}

// ---------------------------------------------------------------------------
// Projection: [K|Q|V] = x @ [Wk|Wq|Wv], tf32 MMA. Block = 256 thr, 128 rows.
// Epilogue writes f16, all three matrices natural [t][h] (coalesced u32).
// ---------------------------------------------------------------------------
__global__ __launch_bounds__(256, 1) void proj_kernel(
    const float* __restrict__ x,
    const float* __restrict__ Wk,
    const float* __restrict__ Wq,
    const float* __restrict__ Wv)
{
    __shared__ float Xs[128 * 36];
    __shared__ float Ws[3 * 32 * 72];

    const int t    = threadIdx.x;
    const int warp = t >> 5;
    const int lane = t & 31;
    const int q    = lane & 3;
    const int r4   = lane >> 2;
    const int row0 = blockIdx.x * 128;
    const float* Wm[3] = {Wk, Wq, Wv};

    float4 c[24];
    #pragma unroll
    for (int i = 0; i < 24; i++) c[i] = make_float4(0.f, 0.f, 0.f, 0.f);

    float4 xr[4], wr[6];
    #pragma unroll
    for (int i = 0; i < 4; i++) {
        int f = t + i * 256, r = f >> 3, c4 = f & 7;
        xr[i] = *(const float4*)&x[(row0 + r) * CDIM + c4 * 4];
    }
    #pragma unroll
    for (int j = 0; j < 6; j++) {
        int g = t + (j & 1) * 256, k = g >> 4, h4 = g & 15;
        wr[j] = *(const float4*)&Wm[j >> 1][k * HDIM + h4 * 4];
    }

    for (int cc = 0; cc < 12; cc++) {
        __syncthreads();
        #pragma unroll
        for (int i = 0; i < 4; i++) {
            int f = t + i * 256, r = f >> 3, c4 = f & 7;
            *(float4*)&Xs[r * 36 + c4 * 4] = make_float4(
                tf32r(xr[i].x), tf32r(xr[i].y), tf32r(xr[i].z), tf32r(xr[i].w));
        }
        #pragma unroll
        for (int j = 0; j < 6; j++) {
            int g = t + (j & 1) * 256, k = g >> 4, h4 = g & 15;
            *(float4*)&Ws[(j >> 1) * 2304 + k * 72 + h4 * 4] = make_float4(
                tf32r(wr[j].x), tf32r(wr[j].y), tf32r(wr[j].z), tf32r(wr[j].w));
        }
        __syncthreads();

        if (cc + 1 < 12) {
            const int c0 = (cc + 1) * 32;
            #pragma unroll
            for (int i = 0; i < 4; i++) {
                int f = t + i * 256, r = f >> 3, c4 = f & 7;
                xr[i] = *(const float4*)&x[(row0 + r) * CDIM + c0 + c4 * 4];
            }
            #pragma unroll
            for (int j = 0; j < 6; j++) {
                int g = t + (j & 1) * 256, k = g >> 4, h4 = g & 15;
                wr[j] = *(const float4*)&Wm[j >> 1][(c0 + k) * HDIM + h4 * 4];
            }
        }

        uint32_t a[4][4];
        #pragma unroll
        for (int kc = 0; kc < 4; kc++) {
            const int rb = (warp * 16 + r4) * 36 + 8 * kc + q;
            a[kc][0] = fu(Xs[rb]);
            a[kc][1] = fu(Xs[rb + 8 * 36]);
            a[kc][2] = fu(Xs[rb + 4]);
            a[kc][3] = fu(Xs[rb + 8 * 36 + 4]);
        }
        #pragma unroll
        for (int mat = 0; mat < 3; mat++)
            #pragma unroll
            for (int nc = 0; nc < 8; nc++)
                #pragma unroll
                for (int kc = 0; kc < 4; kc++) {
                    uint32_t b0 = fu(Ws[mat * 2304 + (8 * kc + q)     * 72 + 8 * nc + r4]);
                    uint32_t b1 = fu(Ws[mat * 2304 + (8 * kc + q + 4) * 72 + 8 * nc + r4]);
                    mma8(c[mat * 8 + nc], a[kc], b0, b1);
                }
    }

    const int row = row0 + warp * 16 + r4;
    #pragma unroll
    for (int nc = 0; nc < 8; nc++) {
        const int col = 8 * nc + 2 * q;
        float4 v = c[nc];
        *(uint32_t*)&g_k[row * HDIM + col]       = packh2(v.x, v.y);
        *(uint32_t*)&g_k[(row + 8) * HDIM + col] = packh2(v.z, v.w);
        v = c[8 + nc];
        *(uint32_t*)&g_q[row * HDIM + col]       = packh2(v.x * 0.125f, v.y * 0.125f);
        *(uint32_t*)&g_q[(row + 8) * HDIM + col] = packh2(v.z * 0.125f, v.w * 0.125f);
        v = c[16 + nc];
        *(uint32_t*)&g_v[row * HDIM + col]       = packh2(v.x, v.y);
        *(uint32_t*)&g_v[(row + 8) * HDIM + col] = packh2(v.z, v.w);
    }
}

// ---------------------------------------------------------------------------
// Flash attention, f16 m16n8k16 warp-MMA + ldmatrix B-frags.
// Block = 128 thr (4 warps), 64 q-rows. grid (32, 32), heavy tiles first.
// K and V staged naturally [key][h] via cp.async, double-buffered, pitch 36
// words (72 halves). K B-frags: ldmatrix.x4; V B-frags: ldmatrix.x4.trans.
// ---------------------------------------------------------------------------
#define PW    36                       // pitch in 32-bit words
#define TILEW (64 * PW)

__global__ __launch_bounds__(128, 3) void attn_kernel(float* __restrict__ out)
{
    __shared__ uint32_t Kbuf[2][TILEW];
    __shared__ uint32_t Vbuf[2][TILEW];

    const int t    = threadIdx.x;
    const int b    = blockIdx.y;
    const int warp = t >> 5;
    const int lane = t & 31;
    const int q    = lane & 3;
    const int r4   = lane >> 2;

    const int qt     = (NQT - 1) - (int)blockIdx.x;   // heavy first
    const int nkt    = qt + 1;
    const int row_lo = qt * 64 + warp * 16 + r4;

    // ldmatrix per-lane invariant byte offsets.
    // K (non-trans): matrix mi = lane>>3; key = 16*ncp + 8*((mi>>1)&1) + (lane&7),
    //                h_start = 16*kc + 8*(mi&1).
    const uint32_t kinv = (uint32_t)((8 * ((lane >> 4) & 1) + (lane & 7)) * PW * 4
                                     + 8 * ((lane >> 3) & 1) * 2);
    // V (trans): key = 16*kc + 8*(mi&1) + (lane&7), h_start = 16*ncp + 8*((mi>>1)&1).
    const uint32_t vinv = (uint32_t)((8 * ((lane >> 3) & 1) + (lane & 7)) * PW * 4
                                     + 8 * ((lane >> 4) & 1) * 2);
    const uint32_t kbs[2] = { smem_u32(Kbuf[0]), smem_u32(Kbuf[1]) };
    const uint32_t vbs[2] = { smem_u32(Vbuf[0]), smem_u32(Vbuf[1]) };

    const __half* kb0 = g_k + (size_t)(b * TDIM) * HDIM;
    const __half* vb0 = g_v + (size_t)(b * TDIM) * HDIM;

    auto stage = [&](int kt, int buf) {
        const __half* kb = kb0 + (size_t)kt * 64 * HDIM;
        const __half* vb = vb0 + (size_t)kt * 64 * HDIM;
        #pragma unroll
        for (int i = 0; i < 4; i++) {
            int f = t + i * 128, r = f >> 3, ch = f & 7;
            cpa16(kbs[buf] + (uint32_t)(r * PW + ch * 4) * 4u, kb + r * HDIM + ch * 8);
            cpa16(vbs[buf] + (uint32_t)(r * PW + ch * 4) * 4u, vb + r * HDIM + ch * 8);
        }
        CPCOMMIT();
    };

    stage(0, 0);

    // Q fragments (f16, already scaled by 0.125)
    uint32_t qa[4][4];
    {
        const __half* qp = g_q + (size_t)(b * TDIM + row_lo) * HDIM;
        #pragma unroll
        for (int kc = 0; kc < 4; kc++) {
            qa[kc][0] = *(const uint32_t*)&qp[16 * kc + 2 * q];
            qa[kc][1] = *(const uint32_t*)&qp[8 * HDIM + 16 * kc + 2 * q];
            qa[kc][2] = *(const uint32_t*)&qp[16 * kc + 2 * q + 8];
            qa[kc][3] = *(const uint32_t*)&qp[8 * HDIM + 16 * kc + 2 * q + 8];
        }
    }

    float4 o[8];
    #pragma unroll
    for (int i = 0; i < 8; i++) o[i] = make_float4(0.f, 0.f, 0.f, 0.f);
    float m0 = -1e30f, m1 = -1e30f, l0 = 0.f, l1 = 0.f;

    for (int kt = 0; kt < nkt; kt++) {
        if (kt + 1 < nkt) { stage(kt + 1, (kt + 1) & 1); CPWAIT(1); }
        else              { CPWAIT(0); }
        __syncthreads();

        const uint32_t kb = kbs[kt & 1] + kinv;
        const uint32_t vb = vbs[kt & 1] + vinv;

        // S = Q @ K^T  (B-frags via ldmatrix.x4, 2 n-tiles per call)
        float4 st[8];
        #pragma unroll
        for (int i = 0; i < 8; i++) st[i] = make_float4(0.f, 0.f, 0.f, 0.f);
        #pragma unroll
        for (int kc = 0; kc < 4; kc++)
            #pragma unroll
            for (int ncp = 0; ncp < 4; ncp++) {
                uint32_t b0, b1, b2, b3;
                ldm4(b0, b1, b2, b3,
                     kb + (uint32_t)(ncp * 16 * PW * 4 + kc * 32));
                mma16(st[2 * ncp],     qa[kc], b0, b1);
                mma16(st[2 * ncp + 1], qa[kc], b2, b3);
            }

        // causal mask: only the diagonal (last) tile clips
        if (kt == nkt - 1) {
            const int cb = kt * 64 + 2 * q;
            #pragma unroll
            for (int nc = 0; nc < 8; nc++) {
                const int col = cb + 8 * nc;
                if (col > row_lo)         st[nc].x = -1e30f;
                if (col + 1 > row_lo)     st[nc].y = -1e30f;
                if (col > row_lo + 8)     st[nc].z = -1e30f;
                if (col + 1 > row_lo + 8) st[nc].w = -1e30f;
            }
        }

        // online softmax (rows r4 / r4+8, spread across the quad)
        float mx0 = st[0].x, mx1 = st[0].z;
        #pragma unroll
        for (int nc = 0; nc < 8; nc++) {
            mx0 = fmaxf(mx0, fmaxf(st[nc].x, st[nc].y));
            mx1 = fmaxf(mx1, fmaxf(st[nc].z, st[nc].w));
        }
        mx0 = fmaxf(mx0, __shfl_xor_sync(0xffffffffu, mx0, 1));
        mx0 = fmaxf(mx0, __shfl_xor_sync(0xffffffffu, mx0, 2));
        mx1 = fmaxf(mx1, __shfl_xor_sync(0xffffffffu, mx1, 1));
        mx1 = fmaxf(mx1, __shfl_xor_sync(0xffffffffu, mx1, 2));
        const float mn0 = fmaxf(m0, mx0), mn1 = fmaxf(m1, mx1);
        const float corr0 = __expf(m0 - mn0), corr1 = __expf(m1 - mn1);
        m0 = mn0; m1 = mn1;

        float s0 = 0.f, s1 = 0.f;
        #pragma unroll
        for (int nc = 0; nc < 8; nc++) {
            st[nc].x = __expf(st[nc].x - mn0);
            st[nc].y = __expf(st[nc].y - mn0);
            st[nc].z = __expf(st[nc].z - mn1);
            st[nc].w = __expf(st[nc].w - mn1);
            s0 += st[nc].x + st[nc].y;
            s1 += st[nc].z + st[nc].w;
        }
        l0 = l0 * corr0 + s0;
        l1 = l1 * corr1 + s1;
        #pragma unroll
        for (int nc = 0; nc < 8; nc++) {
            o[nc].x *= corr0; o[nc].y *= corr0;
            o[nc].z *= corr1; o[nc].w *= corr1;
        }

        // O += P @ V.  P C-frags pack directly into A-frags; V B-frags via
        // ldmatrix.x4.trans from natural [key][h] tile.
        #pragma unroll
        for (int kc = 0; kc < 4; kc++) {
            uint32_t a[4];
            a[0] = packh2(st[2 * kc].x,     st[2 * kc].y);
            a[1] = packh2(st[2 * kc].z,     st[2 * kc].w);
            a[2] = packh2(st[2 * kc + 1].x, st[2 * kc + 1].y);
            a[3] = packh2(st[2 * kc + 1].z, st[2 * kc + 1].w);
            #pragma unroll
            for (int ncp = 0; ncp < 4; ncp++) {
                uint32_t b0, b1, b2, b3;
                ldm4t(b0, b1, b2, b3,
                      vb + (uint32_t)(kc * 16 * PW * 4 + ncp * 32));
                mma16(o[2 * ncp],     a, b0, b1);
                mma16(o[2 * ncp + 1], a, b2, b3);
            }
        }
        __syncthreads();   // reads done before next iteration's cp.async
    }

    // epilogue
    l0 += __shfl_xor_sync(0xffffffffu, l0, 1);
    l0 += __shfl_xor_sync(0xffffffffu, l0, 2);
    l1 += __shfl_xor_sync(0xffffffffu, l1, 1);
    l1 += __shfl_xor_sync(0xffffffffu, l1, 2);
    const float inv0 = 1.0f / l0, inv1 = 1.0f / l1;

    float* ob = out + (size_t)(b * TDIM + row_lo) * HDIM;
    #pragma unroll
    for (int nc = 0; nc < 8; nc++) {
        const int col = 8 * nc + 2 * q;
        *(float2*)&ob[col]            = make_float2(o[nc].x * inv0, o[nc].y * inv0);
        *(float2*)&ob[8 * HDIM + col] = make_float2(o[nc].z * inv1, o[nc].w * inv1);
    }
}

// ---------------------------------------------------------------------------
extern "C" void kernel_launch(void* const* d_in, const int* in_sizes, int n_in,
                              void* d_out, int out_size)
{
    const float* x  = (const float*)d_in[0];
    const float* Wk = (const float*)d_in[1];
    const float* Wq = (const float*)d_in[2];
    const float* Wv = (const float*)d_in[3];
    float* out = (float*)d_out;

    proj_kernel<<<BT / 128, 256>>>(x, Wk, Wq, Wv);

    dim3 agrid(NQT, BATCH);
    attn_kernel<<<agrid, 128>>>(out);
}

// round 10
// speedup vs baseline: 1.8183x; 1.1476x over previous
#include <cuda_runtime.h>
#include <cuda_fp16.h>
#include <cstdint>

#define BATCH 32
#define TDIM  2048
#define CDIM  384
#define HDIM  64
#define BT    (BATCH * TDIM)
#define NQT   32

// Projected activations in f16 (proj rounds once; q pre-scaled by 0.125).
__device__ __align__(256) __half g_q[BT * HDIM];
__device__ __align__(256) __half g_k[BT * HDIM];
__device__ __align__(256) __half g_v[BT * HDIM];

__device__ __forceinline__ uint32_t packh2(float lo, float hi) {
    uint32_t r;
    asm("cvt.rn.f16x2.f32 %0, %1, %2;" : "=r"(r) : "f"(hi), "f"(lo));
    return r;
}
__device__ __forceinline__ uint32_t smem_u32(const void* p) {
    uint32_t a;
    asm("{ .reg .u64 t; cvta.to.shared.u64 t, %1; cvt.u32.u64 %0, t; }"
        : "=r"(a) : "l"(p));
    return a;
}
__device__ __forceinline__ void cpa16(uint32_t dst, const void* src) {
    asm volatile("cp.async.cg.shared.global [%0], [%1], 16;"
                 :: "r"(dst), "l"(src));
}
#define CPCOMMIT() asm volatile("cp.async.commit_group;" ::: "memory")
#define CPWAIT(n)  asm volatile("cp.async.wait_group %0;" :: "n"(n) : "memory")

__device__ __forceinline__ void ldm4(uint32_t& r0, uint32_t& r1,
                                     uint32_t& r2, uint32_t& r3, uint32_t a) {
    asm volatile("ldmatrix.sync.aligned.m8n8.x4.shared.b16 {%0,%1,%2,%3}, [%4];"
                 : "=r"(r0), "=r"(r1), "=r"(r2), "=r"(r3) : "r"(a));
}
__device__ __forceinline__ void ldm4t(uint32_t& r0, uint32_t& r1,
                                      uint32_t& r2, uint32_t& r3, uint32_t a) {
    asm volatile("ldmatrix.sync.aligned.m8n8.x4.trans.shared.b16 {%0,%1,%2,%3}, [%4];"
                 : "=r"(r0), "=r"(r1), "=r"(r2), "=r"(r3) : "r"(a));
}

// f16 m16n8k16, fp32 accum.
// A frag (u32=f16x2): a0(r=l>>2,k=2q..+1) a1(r+8) a2(r,k+8..) a3(r+8,k+8..)
// C frag: c0(r,2q) c1(r,2q+1) c2(r+8,2q) c3(r+8,2q+1)
__device__ __forceinline__ void mma16(float4& c, const uint32_t a[4],
                                      uint32_t b0, uint32_t b1) {
    asm volatile(
        "mma.sync.aligned.m16n8k16.row.col.f32.f16.f16.f32 "
        "{%0,%1,%2,%3}, {%4,%5,%6,%7}, {%8,%9}, {%0,%1,%2,%3};"
        : "+f"(c.x), "+f"(c.y), "+f"(c.z), "+f"(c.w)
        : "r"(a[0]), "r"(a[1]), "r"(a[2]), "r"(a[3]), "r"(b0), "r"(b1));
}

// ---------------------------------------------------------------------------
// Projection: [K|Q|V] = x @ [Wk|Wq|Wv], f16 m16n8k16 + ldmatrix.
// Block = 256 thr (8 warps), 128 rows x 192 cols. K streamed in 12 chunks
// of 32 (f32 gmem -> f16 smem, packed during staging).
// Xs: [128 rows][32 k] f16, pitch 40 f16 (20 words).  A-frags: ldmatrix.x4.
// Ws: [32 k][192 n] f16, pitch 200 f16 (100 words).   B-frags: ldmatrix.x4.trans.
// ---------------------------------------------------------------------------
#define XPW 20     // Xs pitch in words
#define WPW 100    // Ws pitch in words

__global__ __launch_bounds__(256, 1) void proj_kernel(
    const float* __restrict__ x,
    const float* __restrict__ Wk,
    const float* __restrict__ Wq,
    const float* __restrict__ Wv)
{
    __shared__ uint32_t Xs[128 * XPW];
    __shared__ uint32_t Ws[32 * WPW];

    const int t    = threadIdx.x;
    const int warp = t >> 5;
    const int lane = t & 31;
    const int q    = lane & 3;
    const int r4   = lane >> 2;
    const int row0 = blockIdx.x * 128;
    const float* Wm[3] = {Wk, Wq, Wv};

    // ldmatrix invariant byte offsets
    const uint32_t ainv = (uint32_t)((warp * 16 + 8 * ((lane >> 3) & 1) + (lane & 7))
                                     * (XPW * 4) + ((lane >> 4) & 1) * 16);
    const uint32_t winv = (uint32_t)((8 * ((lane >> 3) & 1) + (lane & 7)) * (WPW * 4)
                                     + 8 * ((lane >> 4) & 1) * 2);
    const uint32_t xsb = smem_u32(Xs), wsb = smem_u32(Ws);

    float4 c[24];
    #pragma unroll
    for (int i = 0; i < 24; i++) c[i] = make_float4(0.f, 0.f, 0.f, 0.f);

    // staging maps:
    //  x: thread -> row r = t>>1, half = t&1 (16 f32 = 4 float4 -> 8 u32 f16)
    //  W: 3 slots j: f = t+256j, row = f/24, c8 = f%24 (8 f32 -> 4 u32 f16)
    const int xr_row  = t >> 1, xr_half = t & 1;

    float4 xr[4], wr[6];
    #pragma unroll
    for (int i = 0; i < 4; i++)
        xr[i] = *(const float4*)&x[(row0 + xr_row) * CDIM + xr_half * 16 + i * 4];
    #pragma unroll
    for (int j = 0; j < 3; j++) {
        int f = t + j * 256, row = f / 24, c8 = f % 24;
        const float* wp = &Wm[c8 >> 3][row * HDIM + (c8 & 7) * 8];
        wr[2 * j]     = *(const float4*)wp;
        wr[2 * j + 1] = *(const float4*)(wp + 4);
    }

    for (int cc = 0; cc < 12; cc++) {
        __syncthreads();
        {
            uint4 xp;
            xp.x = packh2(xr[0].x, xr[0].y); xp.y = packh2(xr[0].z, xr[0].w);
            xp.z = packh2(xr[1].x, xr[1].y); xp.w = packh2(xr[1].z, xr[1].w);
            *(uint4*)&Xs[xr_row * XPW + xr_half * 8] = xp;
            xp.x = packh2(xr[2].x, xr[2].y); xp.y = packh2(xr[2].z, xr[2].w);
            xp.z = packh2(xr[3].x, xr[3].y); xp.w = packh2(xr[3].z, xr[3].w);
            *(uint4*)&Xs[xr_row * XPW + xr_half * 8 + 4] = xp;
        }
        #pragma unroll
        for (int j = 0; j < 3; j++) {
            int f = t + j * 256, row = f / 24, c8 = f % 24;
            uint4 wp;
            wp.x = packh2(wr[2*j].x, wr[2*j].y);   wp.y = packh2(wr[2*j].z, wr[2*j].w);
            wp.z = packh2(wr[2*j+1].x, wr[2*j+1].y); wp.w = packh2(wr[2*j+1].z, wr[2*j+1].w);
            *(uint4*)&Ws[row * WPW + c8 * 4] = wp;
        }
        __syncthreads();

        if (cc + 1 < 12) {
            const int c0 = (cc + 1) * 32;
            #pragma unroll
            for (int i = 0; i < 4; i++)
                xr[i] = *(const float4*)&x[(row0 + xr_row) * CDIM + c0
                                           + xr_half * 16 + i * 4];
            #pragma unroll
            for (int j = 0; j < 3; j++) {
                int f = t + j * 256, row = f / 24, c8 = f % 24;
                const float* wp = &Wm[c8 >> 3][(c0 + row) * HDIM + (c8 & 7) * 8];
                wr[2 * j]     = *(const float4*)wp;
                wr[2 * j + 1] = *(const float4*)(wp + 4);
            }
        }

        uint32_t a[2][4];
        ldm4(a[0][0], a[0][1], a[0][2], a[0][3], xsb + ainv);
        ldm4(a[1][0], a[1][1], a[1][2], a[1][3], xsb + ainv + 32);
        #pragma unroll
        for (int nt = 0; nt < 12; nt++)
            #pragma unroll
            for (int kc = 0; kc < 2; kc++) {
                uint32_t b0, b1, b2, b3;
                ldm4t(b0, b1, b2, b3,
                      wsb + winv + (uint32_t)(kc * 16 * WPW * 4 + nt * 32));
                mma16(c[2 * nt],     a[kc], b0, b1);
                mma16(c[2 * nt + 1], a[kc], b2, b3);
            }
    }

    const int row = row0 + warp * 16 + r4;
    __half* outp[3] = {g_k, g_q, g_v};
    #pragma unroll
    for (int idx = 0; idx < 24; idx++) {
        const int gcol = idx * 8 + 2 * q;
        const int mat  = gcol >> 6, col = gcol & 63;
        float4 v = c[idx];
        float sc = (mat == 1) ? 0.125f : 1.0f;   // Q pre-scaled
        *(uint32_t*)&outp[mat][row * HDIM + col]       = packh2(v.x * sc, v.y * sc);
        *(uint32_t*)&outp[mat][(row + 8) * HDIM + col] = packh2(v.z * sc, v.w * sc);
    }
}

// ---------------------------------------------------------------------------
// Flash attention, f16 m16n8k16 + ldmatrix. Block = 128 thr, 64 q-rows.
// 128-key staged tiles (dynamic smem, double-buffered), processed as two
// 64-key sub-passes; fully-masked sub-tiles skipped.
// ---------------------------------------------------------------------------
#define PW     36                      // pitch in words (64 f16 + pad)
#define T128W  (128 * PW)              // words per 128-key tile
#define BUFB   (2 * T128W * 4)         // bytes per buffer (K+V)
#define ASMEM  (2 * BUFB)              // 73728 bytes

__global__ __launch_bounds__(128, 3) void attn_kernel(float* __restrict__ out)
{
    extern __shared__ uint32_t sm[];
    const uint32_t sb = smem_u32(sm);

    const int t    = threadIdx.x;
    const int b    = blockIdx.y;
    const int warp = t >> 5;
    const int lane = t & 31;
    const int q    = lane & 3;
    const int r4   = lane >> 2;

    const int qt     = (NQT - 1) - (int)blockIdx.x;   // heavy first
    const int nkt128 = (qt + 2) >> 1;
    const int row_lo = qt * 64 + warp * 16 + r4;

    const uint32_t kinv = (uint32_t)((8 * ((lane >> 4) & 1) + (lane & 7)) * PW * 4
                                     + 8 * ((lane >> 3) & 1) * 2);
    const uint32_t vinv = (uint32_t)((8 * ((lane >> 3) & 1) + (lane & 7)) * PW * 4
                                     + 8 * ((lane >> 4) & 1) * 2);

    const __half* kb0 = g_k + (size_t)(b * TDIM) * HDIM;
    const __half* vb0 = g_v + (size_t)(b * TDIM) * HDIM;

    auto stage = [&](int kt, int buf) {
        const __half* kb = kb0 + (size_t)kt * 128 * HDIM;
        const __half* vb = vb0 + (size_t)kt * 128 * HDIM;
        const uint32_t kd = sb + (uint32_t)buf * BUFB;
        const uint32_t vd = kd + (uint32_t)T128W * 4;
        #pragma unroll
        for (int i = 0; i < 8; i++) {
            int f = t + i * 128, r = f >> 3, ch = f & 7;
            cpa16(kd + (uint32_t)(r * PW + ch * 4) * 4u, kb + r * HDIM + ch * 8);
            cpa16(vd + (uint32_t)(r * PW + ch * 4) * 4u, vb + r * HDIM + ch * 8);
        }
        CPCOMMIT();
    };

    stage(0, 0);

    uint32_t qa[4][4];
    {
        const __half* qp = g_q + (size_t)(b * TDIM + row_lo) * HDIM;
        #pragma unroll
        for (int kc = 0; kc < 4; kc++) {
            qa[kc][0] = *(const uint32_t*)&qp[16 * kc + 2 * q];
            qa[kc][1] = *(const uint32_t*)&qp[8 * HDIM + 16 * kc + 2 * q];
            qa[kc][2] = *(const uint32_t*)&qp[16 * kc + 2 * q + 8];
            qa[kc][3] = *(const uint32_t*)&qp[8 * HDIM + 16 * kc + 2 * q + 8];
        }
    }

    float4 o[8];
    #pragma unroll
    for (int i = 0; i < 8; i++) o[i] = make_float4(0.f, 0.f, 0.f, 0.f);
    float m0 = -1e30f, m1 = -1e30f, l0 = 0.f, l1 = 0.f;

    for (int kt = 0; kt < nkt128; kt++) {
        if (kt + 1 < nkt128) { stage(kt + 1, (kt + 1) & 1); CPWAIT(1); }
        else                 { CPWAIT(0); }
        __syncthreads();

        const uint32_t kbase = sb + (uint32_t)(kt & 1) * BUFB;

        #pragma unroll 1
        for (int sub = 0; sub < 2; sub++) {
            const int cb = kt * 128 + sub * 64;
            if (cb > qt * 64) break;               // fully masked sub-tile

            const uint32_t kb = kbase + kinv + (uint32_t)(sub * 64 * PW * 4);
            const uint32_t vb = kbase + (uint32_t)T128W * 4 + vinv
                                + (uint32_t)(sub * 64 * PW * 4);

            // S = Q @ K^T
            float4 st[8];
            #pragma unroll
            for (int i = 0; i < 8; i++) st[i] = make_float4(0.f, 0.f, 0.f, 0.f);
            #pragma unroll
            for (int kc = 0; kc < 4; kc++)
                #pragma unroll
                for (int ncp = 0; ncp < 4; ncp++) {
                    uint32_t b0, b1, b2, b3;
                    ldm4(b0, b1, b2, b3,
                         kb + (uint32_t)(ncp * 16 * PW * 4 + kc * 32));
                    mma16(st[2 * ncp],     qa[kc], b0, b1);
                    mma16(st[2 * ncp + 1], qa[kc], b2, b3);
                }

            // causal mask: diagonal sub-tile only
            if (cb == qt * 64) {
                const int cq = cb + 2 * q;
                #pragma unroll
                for (int nc = 0; nc < 8; nc++) {
                    const int col = cq + 8 * nc;
                    if (col > row_lo)         st[nc].x = -1e30f;
                    if (col + 1 > row_lo)     st[nc].y = -1e30f;
                    if (col > row_lo + 8)     st[nc].z = -1e30f;
                    if (col + 1 > row_lo + 8) st[nc].w = -1e30f;
                }
            }

            // online softmax
            float mx0 = st[0].x, mx1 = st[0].z;
            #pragma unroll
            for (int nc = 0; nc < 8; nc++) {
                mx0 = fmaxf(mx0, fmaxf(st[nc].x, st[nc].y));
                mx1 = fmaxf(mx1, fmaxf(st[nc].z, st[nc].w));
            }
            mx0 = fmaxf(mx0, __shfl_xor_sync(0xffffffffu, mx0, 1));
            mx0 = fmaxf(mx0, __shfl_xor_sync(0xffffffffu, mx0, 2));
            mx1 = fmaxf(mx1, __shfl_xor_sync(0xffffffffu, mx1, 1));
            mx1 = fmaxf(mx1, __shfl_xor_sync(0xffffffffu, mx1, 2));
            const float mn0 = fmaxf(m0, mx0), mn1 = fmaxf(m1, mx1);
            const float corr0 = __expf(m0 - mn0), corr1 = __expf(m1 - mn1);
            m0 = mn0; m1 = mn1;

            float s0 = 0.f, s1 = 0.f;
            #pragma unroll
            for (int nc = 0; nc < 8; nc++) {
                st[nc].x = __expf(st[nc].x - mn0);
                st[nc].y = __expf(st[nc].y - mn0);
                st[nc].z = __expf(st[nc].z - mn1);
                st[nc].w = __expf(st[nc].w - mn1);
                s0 += st[nc].x + st[nc].y;
                s1 += st[nc].z + st[nc].w;
            }
            l0 = l0 * corr0 + s0;
            l1 = l1 * corr1 + s1;
            #pragma unroll
            for (int nc = 0; nc < 8; nc++) {
                o[nc].x *= corr0; o[nc].y *= corr0;
                o[nc].z *= corr1; o[nc].w *= corr1;
            }

            // O += P @ V
            #pragma unroll
            for (int kc = 0; kc < 4; kc++) {
                uint32_t a[4];
                a[0] = packh2(st[2 * kc].x,     st[2 * kc].y);
                a[1] = packh2(st[2 * kc].z,     st[2 * kc].w);
                a[2] = packh2(st[2 * kc + 1].x, st[2 * kc + 1].y);
                a[3] = packh2(st[2 * kc + 1].z, st[2 * kc + 1].w);
                #pragma unroll
                for (int ncp = 0; ncp < 4; ncp++) {
                    uint32_t b0, b1, b2, b3;
                    ldm4t(b0, b1, b2, b3,
                          vb + (uint32_t)(kc * 16 * PW * 4 + ncp * 32));
                    mma16(o[2 * ncp],     a, b0, b1);
                    mma16(o[2 * ncp + 1], a, b2, b3);
                }
            }
        }
        __syncthreads();   // reads done before next iteration's cp.async
    }

    // epilogue
    l0 += __shfl_xor_sync(0xffffffffu, l0, 1);
    l0 += __shfl_xor_sync(0xffffffffu, l0, 2);
    l1 += __shfl_xor_sync(0xffffffffu, l1, 1);
    l1 += __shfl_xor_sync(0xffffffffu, l1, 2);
    const float inv0 = 1.0f / l0, inv1 = 1.0f / l1;

    float* ob = out + (size_t)(b * TDIM + row_lo) * HDIM;
    #pragma unroll
    for (int nc = 0; nc < 8; nc++) {
        const int col = 8 * nc + 2 * q;
        *(float2*)&ob[col]            = make_float2(o[nc].x * inv0, o[nc].y * inv0);
        *(float2*)&ob[8 * HDIM + col] = make_float2(o[nc].z * inv1, o[nc].w * inv1);
    }
}

// ---------------------------------------------------------------------------
extern "C" void kernel_launch(void* const* d_in, const int* in_sizes, int n_in,
                              void* d_out, int out_size)
{
    const float* x  = (const float*)d_in[0];
    const float* Wk = (const float*)d_in[1];
    const float* Wq = (const float*)d_in[2];
    const float* Wv = (const float*)d_in[3];
    float* out = (float*)d_out;

    proj_kernel<<<BT / 128, 256>>>(x, Wk, Wq, Wv);

    cudaFuncSetAttribute(attn_kernel,
                         cudaFuncAttributeMaxDynamicSharedMemorySize, ASMEM);
    dim3 agrid(NQT, BATCH);
    attn_kernel<<<agrid, 128, ASMEM>>>(out);
}

// round 11
// speedup vs baseline: 1.8716x; 1.0293x over previous
#include <cuda_runtime.h>
#include <cuda_fp16.h>
#include <cstdint>

#define BATCH 32
#define TDIM  2048
#define CDIM  384
#define HDIM  64
#define BT    (BATCH * TDIM)
#define NQT   32

// Projected activations in f16. q pre-scaled by 0.125*log2(e) (base-2 softmax).
__device__ __align__(256) __half g_q[BT * HDIM];
__device__ __align__(256) __half g_k[BT * HDIM];
__device__ __align__(256) __half g_v[BT * HDIM];

#define QSCALE 0.1803368801111f   // 0.125 * log2(e)

__device__ __forceinline__ uint32_t packh2(float lo, float hi) {
    uint32_t r;
    asm("cvt.rn.f16x2.f32 %0, %1, %2;" : "=r"(r) : "f"(hi), "f"(lo));
    return r;
}
__device__ __forceinline__ float ex2f(float x) {
    float r; asm("ex2.approx.f32 %0, %1;" : "=f"(r) : "f"(x)); return r;
}
__device__ __forceinline__ uint32_t ex2h2(uint32_t x) {
    uint32_t r; asm("ex2.approx.f16x2 %0, %1;" : "=r"(r) : "r"(x)); return r;
}
__device__ __forceinline__ uint32_t smem_u32(const void* p) {
    uint32_t a;
    asm("{ .reg .u64 t; cvta.to.shared.u64 t, %1; cvt.u32.u64 %0, t; }"
        : "=r"(a) : "l"(p));
    return a;
}
__device__ __forceinline__ void cpa16(uint32_t dst, const void* src) {
    asm volatile("cp.async.cg.shared.global [%0], [%1], 16;"
                 :: "r"(dst), "l"(src));
}
#define CPCOMMIT() asm volatile("cp.async.commit_group;" ::: "memory")
#define CPWAIT(n)  asm volatile("cp.async.wait_group %0;" :: "n"(n) : "memory")

__device__ __forceinline__ void ldm4(uint32_t& r0, uint32_t& r1,
                                     uint32_t& r2, uint32_t& r3, uint32_t a) {
    asm volatile("ldmatrix.sync.aligned.m8n8.x4.shared.b16 {%0,%1,%2,%3}, [%4];"
                 : "=r"(r0), "=r"(r1), "=r"(r2), "=r"(r3) : "r"(a));
}
__device__ __forceinline__ void ldm4t(uint32_t& r0, uint32_t& r1,
                                      uint32_t& r2, uint32_t& r3, uint32_t a) {
    asm volatile("ldmatrix.sync.aligned.m8n8.x4.trans.shared.b16 {%0,%1,%2,%3}, [%4];"
                 : "=r"(r0), "=r"(r1), "=r"(r2), "=r"(r3) : "r"(a));
}

// f16 m16n8k16, fp32 accum.
__device__ __forceinline__ void mma16(float4& c, const uint32_t a[4],
                                      uint32_t b0, uint32_t b1) {
    asm volatile(
        "mma.sync.aligned.m16n8k16.row.col.f32.f16.f16.f32 "
        "{%0,%1,%2,%3}, {%4,%5,%6,%7}, {%8,%9}, {%0,%1,%2,%3};"
        : "+f"(c.x), "+f"(c.y), "+f"(c.z), "+f"(c.w)
        : "r"(a[0]), "r"(a[1]), "r"(a[2]), "r"(a[3]), "r"(b0), "r"(b1));
}

// ---------------------------------------------------------------------------
// Projection: [K|Q|V] = x @ [Wk|Wq|Wv], f16 m16n8k16 + ldmatrix.
// Block = 256 thr (8 warps), 128 rows x 192 cols, 12 k-chunks of 32.
// Double-buffered smem (1 barrier/chunk) + 2-chunk-ahead register prefetch.
// ---------------------------------------------------------------------------
#define XPW 20     // Xs pitch in words
#define WPW 100    // Ws pitch in words

__global__ __launch_bounds__(256, 1) void proj_kernel(
    const float* __restrict__ x,
    const float* __restrict__ Wk,
    const float* __restrict__ Wq,
    const float* __restrict__ Wv)
{
    __shared__ uint32_t Xs[2][128 * XPW];
    __shared__ uint32_t Ws[2][32 * WPW];

    const int t    = threadIdx.x;
    const int warp = t >> 5;
    const int lane = t & 31;
    const int q    = lane & 3;
    const int r4   = lane >> 2;
    const int row0 = blockIdx.x * 128;
    const float* Wm[3] = {Wk, Wq, Wv};

    const uint32_t ainv = (uint32_t)((warp * 16 + 8 * ((lane >> 3) & 1) + (lane & 7))
                                     * (XPW * 4) + ((lane >> 4) & 1) * 16);
    const uint32_t winv = (uint32_t)((8 * ((lane >> 3) & 1) + (lane & 7)) * (WPW * 4)
                                     + 8 * ((lane >> 4) & 1) * 2);

    float4 c[24];
    #pragma unroll
    for (int i = 0; i < 24; i++) c[i] = make_float4(0.f, 0.f, 0.f, 0.f);

    const int xr_row = t >> 1, xr_half = t & 1;
    const int wf = t, wrow0 = wf / 24, wc8 = wf % 24;
    const int wrow1 = (wf + 256) / 24, wc8b = (wf + 256) % 24;
    const int wrow2 = (wf + 512) / 24, wc8c = (wf + 512) % 24;

    float4 xr[2][4], wr[2][6];

    auto loadx = [&](float4 xd[4], float4 wd[6], int cc) {
        const int c0 = cc * 32;
        #pragma unroll
        for (int i = 0; i < 4; i++)
            xd[i] = *(const float4*)&x[(row0 + xr_row) * CDIM + c0
                                       + xr_half * 16 + i * 4];
        const float* w0 = &Wm[wc8 >> 3][(c0 + wrow0) * HDIM + (wc8 & 7) * 8];
        wd[0] = *(const float4*)w0; wd[1] = *(const float4*)(w0 + 4);
        const float* w1 = &Wm[wc8b >> 3][(c0 + wrow1) * HDIM + (wc8b & 7) * 8];
        wd[2] = *(const float4*)w1; wd[3] = *(const float4*)(w1 + 4);
        const float* w2 = &Wm[wc8c >> 3][(c0 + wrow2) * HDIM + (wc8c & 7) * 8];
        wd[4] = *(const float4*)w2; wd[5] = *(const float4*)(w2 + 4);
    };

    loadx(xr[0], wr[0], 0);
    loadx(xr[1], wr[1], 1);

    #pragma unroll
    for (int cc = 0; cc < 12; cc++) {
        const int ph = cc & 1;
        // store chunk cc into buffer ph (f32 -> f16 pack)
        {
            float4* xv = xr[ph];
            uint4 xp;
            xp.x = packh2(xv[0].x, xv[0].y); xp.y = packh2(xv[0].z, xv[0].w);
            xp.z = packh2(xv[1].x, xv[1].y); xp.w = packh2(xv[1].z, xv[1].w);
            *(uint4*)&Xs[ph][xr_row * XPW + xr_half * 8] = xp;
            xp.x = packh2(xv[2].x, xv[2].y); xp.y = packh2(xv[2].z, xv[2].w);
            xp.z = packh2(xv[3].x, xv[3].y); xp.w = packh2(xv[3].z, xv[3].w);
            *(uint4*)&Xs[ph][xr_row * XPW + xr_half * 8 + 4] = xp;

            float4* wv = wr[ph];
            uint4 wp;
            wp.x = packh2(wv[0].x, wv[0].y); wp.y = packh2(wv[0].z, wv[0].w);
            wp.z = packh2(wv[1].x, wv[1].y); wp.w = packh2(wv[1].z, wv[1].w);
            *(uint4*)&Ws[ph][wrow0 * WPW + wc8 * 4] = wp;
            wp.x = packh2(wv[2].x, wv[2].y); wp.y = packh2(wv[2].z, wv[2].w);
            wp.z = packh2(wv[3].x, wv[3].y); wp.w = packh2(wv[3].z, wv[3].w);
            *(uint4*)&Ws[ph][wrow1 * WPW + wc8b * 4] = wp;
            wp.x = packh2(wv[4].x, wv[4].y); wp.y = packh2(wv[4].z, wv[4].w);
            wp.z = packh2(wv[5].x, wv[5].y); wp.w = packh2(wv[5].z, wv[5].w);
            *(uint4*)&Ws[ph][wrow2 * WPW + wc8c * 4] = wp;
        }
        __syncthreads();

        if (cc + 2 < 12) loadx(xr[ph], wr[ph], cc + 2);

        const uint32_t xsb = smem_u32(Xs[ph]), wsb = smem_u32(Ws[ph]);
        uint32_t a[2][4];
        ldm4(a[0][0], a[0][1], a[0][2], a[0][3], xsb + ainv);
        ldm4(a[1][0], a[1][1], a[1][2], a[1][3], xsb + ainv + 32);
        #pragma unroll
        for (int nt = 0; nt < 12; nt++)
            #pragma unroll
            for (int kc = 0; kc < 2; kc++) {
                uint32_t b0, b1, b2, b3;
                ldm4t(b0, b1, b2, b3,
                      wsb + winv + (uint32_t)(kc * 16 * WPW * 4 + nt * 32));
                mma16(c[2 * nt],     a[kc], b0, b1);
                mma16(c[2 * nt + 1], a[kc], b2, b3);
            }
    }

    const int row = row0 + warp * 16 + r4;
    __half* outp[3] = {g_k, g_q, g_v};
    #pragma unroll
    for (int idx = 0; idx < 24; idx++) {
        const int gcol = idx * 8 + 2 * q;
        const int mat  = gcol >> 6, col = gcol & 63;
        float4 v = c[idx];
        float sc = (mat == 1) ? QSCALE : 1.0f;   // Q pre-scaled (base-2)
        *(uint32_t*)&outp[mat][row * HDIM + col]       = packh2(v.x * sc, v.y * sc);
        *(uint32_t*)&outp[mat][(row + 8) * HDIM + col] = packh2(v.z * sc, v.w * sc);
    }
}

// ---------------------------------------------------------------------------
// Flash attention, f16 m16n8k16 + ldmatrix, base-2 softmax with f16x2 EX2
// and tensor-core row sums. Block = 128 thr, 64 q-rows, 128-key staging.
// ---------------------------------------------------------------------------
#define PW     36
#define T128W  (128 * PW)
#define BUFB   (2 * T128W * 4)
#define ASMEM  (2 * BUFB)

__global__ __launch_bounds__(128, 3) void attn_kernel(float* __restrict__ out)
{
    extern __shared__ uint32_t sm[];
    const uint32_t sb = smem_u32(sm);

    const int t    = threadIdx.x;
    const int b    = blockIdx.y;
    const int warp = t >> 5;
    const int lane = t & 31;
    const int q    = lane & 3;
    const int r4   = lane >> 2;

    const int qt     = (NQT - 1) - (int)blockIdx.x;
    const int nkt128 = (qt + 2) >> 1;
    const int row_lo = qt * 64 + warp * 16 + r4;

    const uint32_t kinv = (uint32_t)((8 * ((lane >> 4) & 1) + (lane & 7)) * PW * 4
                                     + 8 * ((lane >> 3) & 1) * 2);
    const uint32_t vinv = (uint32_t)((8 * ((lane >> 3) & 1) + (lane & 7)) * PW * 4
                                     + 8 * ((lane >> 4) & 1) * 2);
    const uint32_t bsum = (r4 == 0) ? 0x3C003C00u : 0u;  // ones col 0 B-frag

    const __half* kb0 = g_k + (size_t)(b * TDIM) * HDIM;
    const __half* vb0 = g_v + (size_t)(b * TDIM) * HDIM;

    auto stage = [&](int kt, int buf) {
        const __half* kb = kb0 + (size_t)kt * 128 * HDIM;
        const __half* vb = vb0 + (size_t)kt * 128 * HDIM;
        const uint32_t kd = sb + (uint32_t)buf * BUFB;
        const uint32_t vd = kd + (uint32_t)T128W * 4;
        #pragma unroll
        for (int i = 0; i < 8; i++) {
            int f = t + i * 128, r = f >> 3, ch = f & 7;
            cpa16(kd + (uint32_t)(r * PW + ch * 4) * 4u, kb + r * HDIM + ch * 8);
            cpa16(vd + (uint32_t)(r * PW + ch * 4) * 4u, vb + r * HDIM + ch * 8);
        }
        CPCOMMIT();
    };

    stage(0, 0);

    uint32_t qa[4][4];
    {
        const __half* qp = g_q + (size_t)(b * TDIM + row_lo) * HDIM;
        #pragma unroll
        for (int kc = 0; kc < 4; kc++) {
            qa[kc][0] = *(const uint32_t*)&qp[16 * kc + 2 * q];
            qa[kc][1] = *(const uint32_t*)&qp[8 * HDIM + 16 * kc + 2 * q];
            qa[kc][2] = *(const uint32_t*)&qp[16 * kc + 2 * q + 8];
            qa[kc][3] = *(const uint32_t*)&qp[8 * HDIM + 16 * kc + 2 * q + 8];
        }
    }

    float4 o[8];
    #pragma unroll
    for (int i = 0; i < 8; i++) o[i] = make_float4(0.f, 0.f, 0.f, 0.f);
    float m0 = -1e30f, m1 = -1e30f, l0 = 0.f, l1 = 0.f;

    for (int kt = 0; kt < nkt128; kt++) {
        if (kt + 1 < nkt128) { stage(kt + 1, (kt + 1) & 1); CPWAIT(1); }
        else                 { CPWAIT(0); }
        __syncthreads();

        const uint32_t kbase = sb + (uint32_t)(kt & 1) * BUFB;

        #pragma unroll 1
        for (int sub = 0; sub < 2; sub++) {
            const int cb = kt * 128 + sub * 64;
            if (cb > qt * 64) break;

            const uint32_t kb = kbase + kinv + (uint32_t)(sub * 64 * PW * 4);
            const uint32_t vb = kbase + (uint32_t)T128W * 4 + vinv
                                + (uint32_t)(sub * 64 * PW * 4);

            // S = Q @ K^T  (scores in base-2 units)
            float4 st[8];
            #pragma unroll
            for (int i = 0; i < 8; i++) st[i] = make_float4(0.f, 0.f, 0.f, 0.f);
            #pragma unroll
            for (int kc = 0; kc < 4; kc++)
                #pragma unroll
                for (int ncp = 0; ncp < 4; ncp++) {
                    uint32_t b0, b1, b2, b3;
                    ldm4(b0, b1, b2, b3,
                         kb + (uint32_t)(ncp * 16 * PW * 4 + kc * 32));
                    mma16(st[2 * ncp],     qa[kc], b0, b1);
                    mma16(st[2 * ncp + 1], qa[kc], b2, b3);
                }

            if (cb == qt * 64) {     // diagonal sub-tile: causal mask
                const int cq = cb + 2 * q;
                #pragma unroll
                for (int nc = 0; nc < 8; nc++) {
                    const int col = cq + 8 * nc;
                    if (col > row_lo)         st[nc].x = -1e30f;
                    if (col + 1 > row_lo)     st[nc].y = -1e30f;
                    if (col > row_lo + 8)     st[nc].z = -1e30f;
                    if (col + 1 > row_lo + 8) st[nc].w = -1e30f;
                }
            }

            // online softmax, base 2
            float mx0 = st[0].x, mx1 = st[0].z;
            #pragma unroll
            for (int nc = 0; nc < 8; nc++) {
                mx0 = fmaxf(mx0, fmaxf(st[nc].x, st[nc].y));
                mx1 = fmaxf(mx1, fmaxf(st[nc].z, st[nc].w));
            }
            mx0 = fmaxf(mx0, __shfl_xor_sync(0xffffffffu, mx0, 1));
            mx0 = fmaxf(mx0, __shfl_xor_sync(0xffffffffu, mx0, 2));
            mx1 = fmaxf(mx1, __shfl_xor_sync(0xffffffffu, mx1, 1));
            mx1 = fmaxf(mx1, __shfl_xor_sync(0xffffffffu, mx1, 2));
            const float mn0 = fmaxf(m0, mx0), mn1 = fmaxf(m1, mx1);
            const float corr0 = ex2f(m0 - mn0), corr1 = ex2f(m1 - mn1);
            m0 = mn0; m1 = mn1;

            if (__ballot_sync(0xffffffffu, (corr0 != 1.f) || (corr1 != 1.f))) {
                #pragma unroll
                for (int nc = 0; nc < 8; nc++) {
                    o[nc].x *= corr0; o[nc].y *= corr0;
                    o[nc].z *= corr1; o[nc].w *= corr1;
                }
            }

            // p = 2^(s-mn) in f16x2 (A-frags directly); row sums via HMMA;
            // O += P @ V fused in the same kc loop.
            float4 sums = make_float4(0.f, 0.f, 0.f, 0.f);
            #pragma unroll
            for (int kc = 0; kc < 4; kc++) {
                uint32_t pa[4];
                pa[0] = ex2h2(packh2(st[2*kc].x   - mn0, st[2*kc].y   - mn0));
                pa[1] = ex2h2(packh2(st[2*kc].z   - mn1, st[2*kc].w   - mn1));
                pa[2] = ex2h2(packh2(st[2*kc+1].x - mn0, st[2*kc+1].y - mn0));
                pa[3] = ex2h2(packh2(st[2*kc+1].z - mn1, st[2*kc+1].w - mn1));
                mma16(sums, pa, bsum, bsum);
                #pragma unroll
                for (int ncp = 0; ncp < 4; ncp++) {
                    uint32_t b0, b1, b2, b3;
                    ldm4t(b0, b1, b2, b3,
                          vb + (uint32_t)(kc * 16 * PW * 4 + ncp * 32));
                    mma16(o[2 * ncp],     pa, b0, b1);
                    mma16(o[2 * ncp + 1], pa, b2, b3);
                }
            }
            const float s0 = __shfl_sync(0xffffffffu, sums.x, lane & ~3);
            const float s1 = __shfl_sync(0xffffffffu, sums.z, lane & ~3);
            l0 = l0 * corr0 + s0;
            l1 = l1 * corr1 + s1;
        }
        __syncthreads();
    }

    // epilogue
    const float inv0 = 1.0f / l0, inv1 = 1.0f / l1;
    float* ob = out + (size_t)(b * TDIM + row_lo) * HDIM;
    #pragma unroll
    for (int nc = 0; nc < 8; nc++) {
        const int col = 8 * nc + 2 * q;
        *(float2*)&ob[col]            = make_float2(o[nc].x * inv0, o[nc].y * inv0);
        *(float2*)&ob[8 * HDIM + col] = make_float2(o[nc].z * inv1, o[nc].w * inv1);
    }
}

// ---------------------------------------------------------------------------
extern "C" void kernel_launch(void* const* d_in, const int* in_sizes, int n_in,
                              void* d_out, int out_size)
{
    const float* x  = (const float*)d_in[0];
    const float* Wk = (const float*)d_in[1];
    const float* Wq = (const float*)d_in[2];
    const float* Wv = (const float*)d_in[3];
    float* out = (float*)d_out;

    proj_kernel<<<BT / 128, 256>>>(x, Wk, Wq, Wv);

    cudaFuncSetAttribute(attn_kernel,
                         cudaFuncAttributeMaxDynamicSharedMemorySize, ASMEM);
    dim3 agrid(NQT, BATCH);
    attn_kernel<<<agrid, 128, ASMEM>>>(out);
}